// round 4
// baseline (speedup 1.0000x reference)
#include <cuda_runtime.h>

#define NN 100000
#define NE 1200000
#define NG 512
#define D  64
#define NC 10

// ---------------- scratch (device globals; no allocation) ----------------
__device__ int   g_degi[NN];
__device__ float g_dinv[NN];
__device__ float g_y[NN * D];     // scaled linear output  dinv[n] * (X W)[n]
__device__ float g_agg[NN * D];   // neighbor aggregation
__device__ float g_h[NN * D];     // layer-1 activations
__device__ float g_pool1[NG * D];
__device__ float g_pool2[NG * D];
__device__ int   g_cnti[NG];

// ---------------- kernels ----------------

__global__ void k_init() {
    int i = blockIdx.x * blockDim.x + threadIdx.x;
    if (i < NN) g_degi[i] = 0;
    if (i < NG * D) { g_pool1[i] = 0.0f; g_pool2[i] = 0.0f; }
    if (i < NG) g_cnti[i] = 0;
}

__global__ void k_deg(const int* __restrict__ rows) {
    int e = blockIdx.x * blockDim.x + threadIdx.x;
    if (e >= NE) return;
    unsigned r = (unsigned)rows[e];
    if (r < NN) atomicAdd(&g_degi[r], 1);
}

__global__ void k_prep(const int* __restrict__ batch) {
    int i = blockIdx.x * blockDim.x + threadIdx.x;
    if (i >= NN) return;
    g_dinv[i] = rsqrtf((float)g_degi[i] + 1.0f);   // +1 = self loop
    unsigned g = (unsigned)batch[i];
    if (g < NG) atomicAdd(&g_cnti[g], 1);
}

// g_y[n,d] = dinv[n] * sum_k X[n,k]*W1[k,d]; also zero g_agg
__global__ void k_gemm1(const float* __restrict__ X, const float* __restrict__ W) {
    __shared__ float sW[D * D];
    int t = threadIdx.x;  // 256
    for (int i = t; i < D * D; i += 256) sW[i] = W[i];
    __syncthreads();
    int d = t & 63;
    int n = blockIdx.x * 4 + (t >> 6);
    if (n >= NN) return;
    const float* xr = X + n * D;
    float acc = 0.0f;
#pragma unroll
    for (int k = 0; k < D; k++) acc += xr[k] * sW[k * D + d];
    int idx = n * D + d;
    g_y[idx] = g_dinv[n] * acc;
    g_agg[idx] = 0.0f;
}

// same but source = g_h
__global__ void k_gemm2(const float* __restrict__ W) {
    __shared__ float sW[D * D];
    int t = threadIdx.x;
    for (int i = t; i < D * D; i += 256) sW[i] = W[i];
    __syncthreads();
    int d = t & 63;
    int n = blockIdx.x * 4 + (t >> 6);
    if (n >= NN) return;
    const float* xr = g_h + n * D;
    float acc = 0.0f;
#pragma unroll
    for (int k = 0; k < D; k++) acc += xr[k] * sW[k * D + d];
    int idx = n * D + d;
    g_y[idx] = g_dinv[n] * acc;
    g_agg[idx] = 0.0f;
}

// one warp per edge: g_agg[row] += g_y[col]
__global__ void k_scatter(const int* __restrict__ rows,
                          const int* __restrict__ cols) {
    int warp = (blockIdx.x * blockDim.x + threadIdx.x) >> 5;
    int lane = threadIdx.x & 31;
    if (warp >= NE) return;
    unsigned r = (unsigned)rows[warp];
    unsigned c = (unsigned)cols[warp];
    if (r >= NN || c >= NN) return;
    float v0 = g_y[c * D + lane];
    float v1 = g_y[c * D + 32 + lane];
    atomicAdd(&g_agg[r * D + lane], v0);
    atomicAdd(&g_agg[r * D + 32 + lane], v1);
}

__global__ void k_fin1(const float* __restrict__ b, const int* __restrict__ batch) {
    int idx = blockIdx.x * blockDim.x + threadIdx.x;
    if (idx >= NN * D) return;
    int n = idx >> 6, d = idx & 63;
    float h = fmaxf(g_dinv[n] * (g_agg[idx] + g_y[idx]) + b[d], 0.0f);
    g_h[idx] = h;
    unsigned g = (unsigned)batch[n];
    if (g < NG) atomicAdd(&g_pool1[g * D + d], h);
}

__global__ void k_fin2(const float* __restrict__ b, const int* __restrict__ batch) {
    int idx = blockIdx.x * blockDim.x + threadIdx.x;
    if (idx >= NN * D) return;
    int n = idx >> 6, d = idx & 63;
    float h = fmaxf(g_dinv[n] * (g_agg[idx] + g_y[idx]) + b[d], 0.0f);
    unsigned g = (unsigned)batch[n];
    if (g < NG) atomicAdd(&g_pool2[g * D + d], h);
}

// one warp per graph: mean pool combine, head linear, relu, log_softmax
__global__ void k_head(const float* __restrict__ Wl, const float* __restrict__ bl,
                       float* __restrict__ out) {
    int g = blockIdx.x;
    int lane = threadIdx.x;  // 32
    float denom = fmaxf((float)g_cnti[g], 1.0f);
    float v0 = (g_pool1[g * D + lane] + g_pool2[g * D + lane]) / denom;
    float v1 = (g_pool1[g * D + 32 + lane] + g_pool2[g * D + 32 + lane]) / denom;
    float z = (lane < NC) ? bl[lane] : 0.0f;
#pragma unroll
    for (int d = 0; d < 32; d++) {
        float a0 = __shfl_sync(0xffffffffu, v0, d);
        float a1 = __shfl_sync(0xffffffffu, v1, d);
        if (lane < NC) z += a0 * Wl[d * NC + lane] + a1 * Wl[(d + 32) * NC + lane];
    }
    if (lane < NC) z = fmaxf(z, 0.0f);
    float zm = (lane < NC) ? z : -1e30f;
#pragma unroll
    for (int off = 16; off; off >>= 1)
        zm = fmaxf(zm, __shfl_xor_sync(0xffffffffu, zm, off));
    float e = (lane < NC) ? expf(z - zm) : 0.0f;
#pragma unroll
    for (int off = 16; off; off >>= 1)
        e += __shfl_xor_sync(0xffffffffu, e, off);
    if (lane < NC) out[g * NC + lane] = z - zm - logf(e);
}

// ---------------- launch ----------------

extern "C" void kernel_launch(void* const* d_in, const int* in_sizes, int n_in,
                              void* d_out, int out_size) {
    const float* x     = (const float*)d_in[0];
    const int*   eidx  = (const int*)d_in[1];    // int32! (JAX x64 disabled)
    const int*   batch = (const int*)d_in[2];
    const float* W1    = (const float*)d_in[3];
    const float* b1    = (const float*)d_in[4];
    const float* W2    = (const float*)d_in[5];
    const float* b2    = (const float*)d_in[6];
    const float* Wl    = (const float*)d_in[7];
    const float* bl    = (const float*)d_in[8];
    float* out = (float*)d_out;

    const int* rows = eidx;        // edge_index[0] = targets
    const int* cols = eidx + NE;   // edge_index[1] = sources

    k_init<<<(NN + 255) / 256, 256>>>();
    k_deg<<<(NE + 255) / 256, 256>>>(rows);
    k_prep<<<(NN + 255) / 256, 256>>>(batch);

    // conv1
    k_gemm1<<<NN / 4, 256>>>(x, W1);
    k_scatter<<<(NE * 32) / 256, 256>>>(rows, cols);
    k_fin1<<<(NN * D) / 256, 256>>>(b1, batch);

    // conv2
    k_gemm2<<<NN / 4, 256>>>(W2);
    k_scatter<<<(NE * 32) / 256, 256>>>(rows, cols);
    k_fin2<<<(NN * D) / 256, 256>>>(b2, batch);

    // head
    k_head<<<NG, 32>>>(Wl, bl, out);
}

// round 5
// speedup vs baseline: 1.3426x; 1.3426x over previous
#include <cuda_runtime.h>

#define NN 100000
#define NE 1200000
#define NG 512
#define D  64
#define NC 10

// ---------------- scratch (device globals; no allocation) ----------------
__device__ int   g_degi[NN];
__device__ float g_dinv[NN];
__device__ float g_y[NN * D];     // scaled linear output  dinv[n] * (X W)[n]
__device__ float g_agg[NN * D];   // neighbor aggregation
__device__ float g_h[NN * D];     // layer-1 activations
__device__ float g_pool1[NG * D];
__device__ float g_pool2[NG * D];
__device__ int   g_cnti[NG];

__device__ __forceinline__ void red_v4(float4* dst, float4 v) {
    asm volatile("red.global.add.v4.f32 [%0], {%1,%2,%3,%4};"
                 :: "l"(dst), "f"(v.x), "f"(v.y), "f"(v.z), "f"(v.w) : "memory");
}

// ---------------- kernels ----------------

__global__ void k_init() {
    int i = blockIdx.x * blockDim.x + threadIdx.x;
    if (i < NN) g_degi[i] = 0;
    if (i < NG * D) { g_pool1[i] = 0.0f; g_pool2[i] = 0.0f; }
    if (i < NG) g_cnti[i] = 0;
}

__global__ void k_deg(const int* __restrict__ rows) {
    int e = blockIdx.x * blockDim.x + threadIdx.x;
    if (e >= NE) return;
    unsigned r = (unsigned)rows[e];
    if (r < NN) atomicAdd(&g_degi[r], 1);
}

__global__ void k_prep(const int* __restrict__ batch) {
    int i = blockIdx.x * blockDim.x + threadIdx.x;
    if (i >= NN) return;
    g_dinv[i] = rsqrtf((float)g_degi[i] + 1.0f);   // +1 = self loop
    unsigned g = (unsigned)batch[i];
    if (g < NG) atomicAdd(&g_cnti[g], 1);
}

// Register-tiled GEMM: 256 thr = 8 warps; warp handles 4 rows; lane handles
// (row = lane>>3, col-group grp = lane&7 -> 8 outputs). x row held in regs
// across the 8 lanes of its group, broadcast via shfl(width=8).
// Writes g_y = dinv * (X W), zeroes g_agg.
__device__ __forceinline__ void gemm_body(const float* __restrict__ X,
                                          const float* __restrict__ W) {
    __shared__ float sW[D * D];
    int t = threadIdx.x;
    for (int i = t; i < D * D; i += 256) sW[i] = W[i];
    __syncthreads();
    int warp = t >> 5, lane = t & 31;
    int n = blockIdx.x * 32 + warp * 4 + (lane >> 3);   // NN % 32 == 0
    int grp = lane & 7;
    const float4* xr = (const float4*)(X + n * D);
    float4 xa = xr[grp * 2];
    float4 xb = xr[grp * 2 + 1];
    float xv[8] = {xa.x, xa.y, xa.z, xa.w, xb.x, xb.y, xb.z, xb.w};
    float acc[8] = {0, 0, 0, 0, 0, 0, 0, 0};
    int d0 = grp * 8;
#pragma unroll
    for (int k = 0; k < D; k++) {
        float xk = __shfl_sync(0xffffffffu, xv[k & 7], k >> 3, 8);
        const float4* wr = (const float4*)(sW + k * D + d0);
        float4 w0 = wr[0], w1 = wr[1];
        acc[0] += xk * w0.x; acc[1] += xk * w0.y;
        acc[2] += xk * w0.z; acc[3] += xk * w0.w;
        acc[4] += xk * w1.x; acc[5] += xk * w1.y;
        acc[6] += xk * w1.z; acc[7] += xk * w1.w;
    }
    float s = g_dinv[n];
    float4 o0 = make_float4(s * acc[0], s * acc[1], s * acc[2], s * acc[3]);
    float4 o1 = make_float4(s * acc[4], s * acc[5], s * acc[6], s * acc[7]);
    float4* yout = (float4*)(g_y + n * D + d0);
    yout[0] = o0; yout[1] = o1;
    float4 z4 = make_float4(0.f, 0.f, 0.f, 0.f);
    float4* aout = (float4*)(g_agg + n * D + d0);
    aout[0] = z4; aout[1] = z4;
}

__global__ void k_gemm1(const float* __restrict__ X, const float* __restrict__ W) {
    gemm_body(X, W);
}
__global__ void k_gemm2(const float* __restrict__ W) {
    gemm_body(g_h, W);
}

// 16 threads per edge: g_agg[row] += g_y[col], vector (v4) reductions
__global__ void k_scatter(const int* __restrict__ rows,
                          const int* __restrict__ cols) {
    int idx = blockIdx.x * blockDim.x + threadIdx.x;
    int e = idx >> 4;
    int q = idx & 15;
    if (e >= NE) return;
    unsigned r = (unsigned)rows[e];
    unsigned c = (unsigned)cols[e];
    if (r >= NN || c >= NN) return;
    float4 v = ((const float4*)g_y)[c * 16 + q];
    red_v4(((float4*)g_agg) + r * 16 + q, v);
}

// h = relu(dinv*(agg + y_self) + b); vectorized; pool via v4 red
__global__ void k_fin1(const float* __restrict__ b, const int* __restrict__ batch) {
    int i4 = blockIdx.x * blockDim.x + threadIdx.x;   // over NN*16
    if (i4 >= NN * 16) return;
    int n = i4 >> 4, q = i4 & 15;
    float4 a = ((const float4*)g_agg)[i4];
    float4 y = ((const float4*)g_y)[i4];
    float4 bb = ((const float4*)b)[q];
    float s = g_dinv[n];
    float4 h;
    h.x = fmaxf(s * (a.x + y.x) + bb.x, 0.0f);
    h.y = fmaxf(s * (a.y + y.y) + bb.y, 0.0f);
    h.z = fmaxf(s * (a.z + y.z) + bb.z, 0.0f);
    h.w = fmaxf(s * (a.w + y.w) + bb.w, 0.0f);
    ((float4*)g_h)[i4] = h;
    unsigned g = (unsigned)batch[n];
    if (g < NG) red_v4(((float4*)g_pool1) + g * 16 + q, h);
}

__global__ void k_fin2(const float* __restrict__ b, const int* __restrict__ batch) {
    int i4 = blockIdx.x * blockDim.x + threadIdx.x;
    if (i4 >= NN * 16) return;
    int n = i4 >> 4, q = i4 & 15;
    float4 a = ((const float4*)g_agg)[i4];
    float4 y = ((const float4*)g_y)[i4];
    float4 bb = ((const float4*)b)[q];
    float s = g_dinv[n];
    float4 h;
    h.x = fmaxf(s * (a.x + y.x) + bb.x, 0.0f);
    h.y = fmaxf(s * (a.y + y.y) + bb.y, 0.0f);
    h.z = fmaxf(s * (a.z + y.z) + bb.z, 0.0f);
    h.w = fmaxf(s * (a.w + y.w) + bb.w, 0.0f);
    unsigned g = (unsigned)batch[n];
    if (g < NG) red_v4(((float4*)g_pool2) + g * 16 + q, h);
}

// one warp per graph: mean pool combine, head linear, relu, log_softmax
__global__ void k_head(const float* __restrict__ Wl, const float* __restrict__ bl,
                       float* __restrict__ out) {
    int g = blockIdx.x;
    int lane = threadIdx.x;  // 32
    float denom = fmaxf((float)g_cnti[g], 1.0f);
    float v0 = (g_pool1[g * D + lane] + g_pool2[g * D + lane]) / denom;
    float v1 = (g_pool1[g * D + 32 + lane] + g_pool2[g * D + 32 + lane]) / denom;
    float z = (lane < NC) ? bl[lane] : 0.0f;
#pragma unroll
    for (int d = 0; d < 32; d++) {
        float a0 = __shfl_sync(0xffffffffu, v0, d);
        float a1 = __shfl_sync(0xffffffffu, v1, d);
        if (lane < NC) z += a0 * Wl[d * NC + lane] + a1 * Wl[(d + 32) * NC + lane];
    }
    if (lane < NC) z = fmaxf(z, 0.0f);
    float zm = (lane < NC) ? z : -1e30f;
#pragma unroll
    for (int off = 16; off; off >>= 1)
        zm = fmaxf(zm, __shfl_xor_sync(0xffffffffu, zm, off));
    float e = (lane < NC) ? expf(z - zm) : 0.0f;
#pragma unroll
    for (int off = 16; off; off >>= 1)
        e += __shfl_xor_sync(0xffffffffu, e, off);
    if (lane < NC) out[g * NC + lane] = z - zm - logf(e);
}

// ---------------- launch ----------------

extern "C" void kernel_launch(void* const* d_in, const int* in_sizes, int n_in,
                              void* d_out, int out_size) {
    const float* x     = (const float*)d_in[0];
    const int*   eidx  = (const int*)d_in[1];    // int32 (JAX x64 disabled)
    const int*   batch = (const int*)d_in[2];
    const float* W1    = (const float*)d_in[3];
    const float* b1    = (const float*)d_in[4];
    const float* W2    = (const float*)d_in[5];
    const float* b2    = (const float*)d_in[6];
    const float* Wl    = (const float*)d_in[7];
    const float* bl    = (const float*)d_in[8];
    float* out = (float*)d_out;

    const int* rows = eidx;        // edge_index[0] = targets
    const int* cols = eidx + NE;   // edge_index[1] = sources

    k_init<<<(NN + 255) / 256, 256>>>();
    k_deg<<<(NE + 255) / 256, 256>>>(rows);
    k_prep<<<(NN + 255) / 256, 256>>>(batch);

    // conv1
    k_gemm1<<<NN / 32, 256>>>(x, W1);                 // 3125 blocks
    k_scatter<<<(NE * 16) / 256, 256>>>(rows, cols);  // 75000 blocks
    k_fin1<<<(NN * 16) / 256, 256>>>(b1, batch);      // 6250 blocks

    // conv2
    k_gemm2<<<NN / 32, 256>>>(W2);
    k_scatter<<<(NE * 16) / 256, 256>>>(rows, cols);
    k_fin2<<<(NN * 16) / 256, 256>>>(b2, batch);

    // head
    k_head<<<NG, 32>>>(Wl, bl, out);
}

// round 6
// speedup vs baseline: 1.9558x; 1.4567x over previous
#include <cuda_runtime.h>

#define NN 100000
#define NE 1200000
#define NG 512
#define D  64
#define NC 10
#define RP 65   // padded smem row (conflict-free column reads)

// ---------------- scratch (device globals; no allocation) ----------------
__device__ int   g_degi[NN];
__device__ float g_dinv[NN];
__device__ float g_y[NN * D];     // scaled linear output  dinv[n] * (X W)[n]
__device__ float g_agg[NN * D];   // neighbor aggregation
__device__ float g_h[NN * D];     // layer-1 activations
__device__ float g_pool1[NG * D];
__device__ float g_pool2[NG * D];
__device__ int   g_cnti[NG];

__device__ __forceinline__ void red_v4(float4* dst, float4 v) {
    asm volatile("red.global.add.v4.f32 [%0], {%1,%2,%3,%4};"
                 :: "l"(dst), "f"(v.x), "f"(v.y), "f"(v.z), "f"(v.w) : "memory");
}

// ---------------- kernels ----------------

__global__ void k_init() {
    int i = blockIdx.x * blockDim.x + threadIdx.x;
    if (i < NN) g_degi[i] = 0;
    if (i < NG * D) { g_pool1[i] = 0.0f; g_pool2[i] = 0.0f; }
    if (i < NG) g_cnti[i] = 0;
}

__global__ void k_deg(const int* __restrict__ rows) {
    int e = blockIdx.x * blockDim.x + threadIdx.x;
    if (e >= NE) return;
    unsigned r = (unsigned)rows[e];
    if (r < NN) atomicAdd(&g_degi[r], 1);
}

__global__ void k_prep(const int* __restrict__ batch) {
    int i = blockIdx.x * blockDim.x + threadIdx.x;
    if (i >= NN) return;
    g_dinv[i] = rsqrtf((float)g_degi[i] + 1.0f);   // +1 = self loop
    unsigned g = (unsigned)batch[i];
    if (g < NG) atomicAdd(&g_cnti[g], 1);
}

// GEMM: block = 256 thr = 8 warps, tile = 64 rows x 64 cols.
// Warp w: rows (w&1)*32 + lane (32 rows), cols (w>>1)*16 .. +16.
// x[r][k] read per-lane from padded smem (conflict-free);
// W row chunk read as 4 warp-uniform (broadcast) LDS.128.
// Writes g_y = dinv * (X W); zeroes g_agg.
__device__ __forceinline__ void gemm_body(const float* __restrict__ X,
                                          const float* __restrict__ W,
                                          int n0) {
    __shared__ float sW[D * D];
    __shared__ float sX[64 * RP];
    int t = threadIdx.x;
    for (int i = t; i < 1024; i += 256)
        ((float4*)sW)[i] = ((const float4*)W)[i];
    for (int i = t; i < 1024; i += 256) {
        int r = i >> 4, c4 = i & 15;
        float4 v = make_float4(0.f, 0.f, 0.f, 0.f);
        if (n0 + r < NN) v = ((const float4*)X)[(n0 + r) * 16 + c4];
        float* dst = &sX[r * RP + c4 * 4];
        dst[0] = v.x; dst[1] = v.y; dst[2] = v.z; dst[3] = v.w;
    }
    __syncthreads();

    int w = t >> 5, lane = t & 31;
    int r = (w & 1) * 32 + lane;
    int c0 = (w >> 1) * 16;
    float acc[16];
#pragma unroll
    for (int i = 0; i < 16; i++) acc[i] = 0.0f;

    const float* xrow = &sX[r * RP];
#pragma unroll
    for (int k = 0; k < D; k++) {
        float xk = xrow[k];
        const float4* wr = (const float4*)&sW[k * D + c0];
        float4 w0 = wr[0], w1 = wr[1], w2 = wr[2], w3 = wr[3];
        acc[0]  += xk * w0.x; acc[1]  += xk * w0.y;
        acc[2]  += xk * w0.z; acc[3]  += xk * w0.w;
        acc[4]  += xk * w1.x; acc[5]  += xk * w1.y;
        acc[6]  += xk * w1.z; acc[7]  += xk * w1.w;
        acc[8]  += xk * w2.x; acc[9]  += xk * w2.y;
        acc[10] += xk * w2.z; acc[11] += xk * w2.w;
        acc[12] += xk * w3.x; acc[13] += xk * w3.y;
        acc[14] += xk * w3.z; acc[15] += xk * w3.w;
    }

    int n = n0 + r;
    if (n < NN) {
        float s = g_dinv[n];
        float4* yo = (float4*)(g_y + n * D + c0);
        float4* ao = (float4*)(g_agg + n * D + c0);
        float4 z4 = make_float4(0.f, 0.f, 0.f, 0.f);
#pragma unroll
        for (int j = 0; j < 4; j++) {
            yo[j] = make_float4(s * acc[j*4], s * acc[j*4+1],
                                s * acc[j*4+2], s * acc[j*4+3]);
            ao[j] = z4;
        }
    }
}

__global__ void __launch_bounds__(256) k_gemm1(const float* __restrict__ X,
                                               const float* __restrict__ W) {
    gemm_body(X, W, blockIdx.x * 64);
}
__global__ void __launch_bounds__(256) k_gemm2(const float* __restrict__ W) {
    gemm_body(g_h, W, blockIdx.x * 64);
}

// 16 threads per edge: g_agg[row] += g_y[col], vector (v4) reductions
__global__ void k_scatter(const int* __restrict__ rows,
                          const int* __restrict__ cols) {
    int idx = blockIdx.x * blockDim.x + threadIdx.x;
    int e = idx >> 4;
    int q = idx & 15;
    if (e >= NE) return;
    unsigned r = (unsigned)rows[e];
    unsigned c = (unsigned)cols[e];
    if (r >= NN || c >= NN) return;
    float4 v = ((const float4*)g_y)[c * 16 + q];
    red_v4(((float4*)g_agg) + r * 16 + q, v);
}

// h = relu(dinv*(agg + y_self) + b); vectorized; pool via v4 red
__global__ void k_fin1(const float* __restrict__ b, const int* __restrict__ batch) {
    int i4 = blockIdx.x * blockDim.x + threadIdx.x;   // over NN*16
    if (i4 >= NN * 16) return;
    int n = i4 >> 4, q = i4 & 15;
    float4 a = ((const float4*)g_agg)[i4];
    float4 y = ((const float4*)g_y)[i4];
    float4 bb = ((const float4*)b)[q];
    float s = g_dinv[n];
    float4 h;
    h.x = fmaxf(s * (a.x + y.x) + bb.x, 0.0f);
    h.y = fmaxf(s * (a.y + y.y) + bb.y, 0.0f);
    h.z = fmaxf(s * (a.z + y.z) + bb.z, 0.0f);
    h.w = fmaxf(s * (a.w + y.w) + bb.w, 0.0f);
    ((float4*)g_h)[i4] = h;
    unsigned g = (unsigned)batch[n];
    if (g < NG) red_v4(((float4*)g_pool1) + g * 16 + q, h);
}

__global__ void k_fin2(const float* __restrict__ b, const int* __restrict__ batch) {
    int i4 = blockIdx.x * blockDim.x + threadIdx.x;
    if (i4 >= NN * 16) return;
    int n = i4 >> 4, q = i4 & 15;
    float4 a = ((const float4*)g_agg)[i4];
    float4 y = ((const float4*)g_y)[i4];
    float4 bb = ((const float4*)b)[q];
    float s = g_dinv[n];
    float4 h;
    h.x = fmaxf(s * (a.x + y.x) + bb.x, 0.0f);
    h.y = fmaxf(s * (a.y + y.y) + bb.y, 0.0f);
    h.z = fmaxf(s * (a.z + y.z) + bb.z, 0.0f);
    h.w = fmaxf(s * (a.w + y.w) + bb.w, 0.0f);
    unsigned g = (unsigned)batch[n];
    if (g < NG) red_v4(((float4*)g_pool2) + g * 16 + q, h);
}

// one warp per graph: mean pool combine, head linear, relu, log_softmax
__global__ void k_head(const float* __restrict__ Wl, const float* __restrict__ bl,
                       float* __restrict__ out) {
    int g = blockIdx.x;
    int lane = threadIdx.x;  // 32
    float denom = fmaxf((float)g_cnti[g], 1.0f);
    float v0 = (g_pool1[g * D + lane] + g_pool2[g * D + lane]) / denom;
    float v1 = (g_pool1[g * D + 32 + lane] + g_pool2[g * D + 32 + lane]) / denom;
    float z = (lane < NC) ? bl[lane] : 0.0f;
#pragma unroll
    for (int d = 0; d < 32; d++) {
        float a0 = __shfl_sync(0xffffffffu, v0, d);
        float a1 = __shfl_sync(0xffffffffu, v1, d);
        if (lane < NC) z += a0 * Wl[d * NC + lane] + a1 * Wl[(d + 32) * NC + lane];
    }
    if (lane < NC) z = fmaxf(z, 0.0f);
    float zm = (lane < NC) ? z : -1e30f;
#pragma unroll
    for (int off = 16; off; off >>= 1)
        zm = fmaxf(zm, __shfl_xor_sync(0xffffffffu, zm, off));
    float e = (lane < NC) ? expf(z - zm) : 0.0f;
#pragma unroll
    for (int off = 16; off; off >>= 1)
        e += __shfl_xor_sync(0xffffffffu, e, off);
    if (lane < NC) out[g * NC + lane] = z - zm - logf(e);
}

// ---------------- launch ----------------

extern "C" void kernel_launch(void* const* d_in, const int* in_sizes, int n_in,
                              void* d_out, int out_size) {
    const float* x     = (const float*)d_in[0];
    const int*   eidx  = (const int*)d_in[1];    // int32 (JAX x64 disabled)
    const int*   batch = (const int*)d_in[2];
    const float* W1    = (const float*)d_in[3];
    const float* b1    = (const float*)d_in[4];
    const float* W2    = (const float*)d_in[5];
    const float* b2    = (const float*)d_in[6];
    const float* Wl    = (const float*)d_in[7];
    const float* bl    = (const float*)d_in[8];
    float* out = (float*)d_out;

    const int* rows = eidx;        // edge_index[0] = targets
    const int* cols = eidx + NE;   // edge_index[1] = sources

    const int GB = (NN + 63) / 64;   // 1563 gemm blocks

    k_init<<<(NN + 255) / 256, 256>>>();
    k_deg<<<(NE + 255) / 256, 256>>>(rows);
    k_prep<<<(NN + 255) / 256, 256>>>(batch);

    // conv1
    k_gemm1<<<GB, 256>>>(x, W1);
    k_scatter<<<(NE * 16) / 256, 256>>>(rows, cols);
    k_fin1<<<(NN * 16) / 256, 256>>>(b1, batch);

    // conv2
    k_gemm2<<<GB, 256>>>(W2);
    k_scatter<<<(NE * 16) / 256, 256>>>(rows, cols);
    k_fin2<<<(NN * 16) / 256, 256>>>(b2, batch);

    // head
    k_head<<<NG, 32>>>(Wl, bl, out);
}

// round 7
// speedup vs baseline: 2.9916x; 1.5296x over previous
#include <cuda_runtime.h>

#define NN 100000
#define NE 1200000
#define NG 512
#define D  64
#define NC 10
#define RP 65            // padded smem row (conflict-free column reads)
#define NB 391           // scan blocks = ceil(NN/256)

// ---------------- scratch (device globals; no allocation) ----------------
__device__ int   g_degi[NN];
__device__ float g_dinv[NN];
__device__ float g_y[NN * D];     // scaled linear output  dinv[n] * (X W)[n]
__device__ float g_h[NN * D];     // layer-1 activations
__device__ float g_pool1[NG * D];
__device__ float g_pool2[NG * D];
__device__ int   g_cnti[NG];
// CSR
__device__ int   g_scan[NN];
__device__ int   g_bsum[NB];
__device__ int   g_boff[NB];
__device__ int   g_start[NN + 1];
__device__ int   g_pos[NN];
__device__ int   g_ecol[NE];

__device__ __forceinline__ void red_v4(float4* dst, float4 v) {
    asm volatile("red.global.add.v4.f32 [%0], {%1,%2,%3,%4};"
                 :: "l"(dst), "f"(v.x), "f"(v.y), "f"(v.z), "f"(v.w) : "memory");
}

// ---------------- setup kernels ----------------

__global__ void k_init() {
    int i = blockIdx.x * blockDim.x + threadIdx.x;
    if (i < NN) g_degi[i] = 0;
    if (i < NG * D) { g_pool1[i] = 0.0f; g_pool2[i] = 0.0f; }
    if (i < NG) g_cnti[i] = 0;
}

__global__ void k_deg(const int* __restrict__ rows) {
    int e = blockIdx.x * blockDim.x + threadIdx.x;
    if (e >= NE) return;
    unsigned r = (unsigned)rows[e];
    if (r < NN) atomicAdd(&g_degi[r], 1);
}

__global__ void k_prep(const int* __restrict__ batch) {
    int i = blockIdx.x * blockDim.x + threadIdx.x;
    if (i >= NN) return;
    g_dinv[i] = rsqrtf((float)g_degi[i] + 1.0f);   // +1 = self loop
    unsigned g = (unsigned)batch[i];
    if (g < NG) atomicAdd(&g_cnti[g], 1);
}

// per-block inclusive scan of degrees
__global__ void k_scanA() {
    __shared__ int s[256];
    int t = threadIdx.x;
    int i = blockIdx.x * 256 + t;
    int d = (i < NN) ? g_degi[i] : 0;
    s[t] = d;
    __syncthreads();
#pragma unroll
    for (int off = 1; off < 256; off <<= 1) {
        int v = (t >= off) ? s[t - off] : 0;
        __syncthreads();
        s[t] += v;
        __syncthreads();
    }
    if (i < NN) g_scan[i] = s[t];
    if (t == 255) g_bsum[blockIdx.x] = s[255];
}

// single-block exclusive scan of block sums
__global__ void k_scanB() {
    __shared__ int s[512];
    int t = threadIdx.x;  // 512
    s[t] = (t < NB) ? g_bsum[t] : 0;
    __syncthreads();
#pragma unroll
    for (int off = 1; off < 512; off <<= 1) {
        int v = (t >= off) ? s[t - off] : 0;
        __syncthreads();
        s[t] += v;
        __syncthreads();
    }
    if (t < NB) g_boff[t] = (t == 0) ? 0 : s[t - 1];
    if (t == 511) g_start[NN] = s[511];
}

__global__ void k_scanC() {
    int i = blockIdx.x * blockDim.x + threadIdx.x;
    if (i >= NN) return;
    int st = g_scan[i] - g_degi[i] + g_boff[i >> 8];
    g_start[i] = st;
    g_pos[i] = st;
}

__global__ void k_fill(const int* __restrict__ rows, const int* __restrict__ cols) {
    int e = blockIdx.x * blockDim.x + threadIdx.x;
    if (e >= NE) return;
    unsigned r = (unsigned)rows[e];
    if (r >= NN) return;
    int p = atomicAdd(&g_pos[r], 1);
    g_ecol[p] = cols[e];
}

// ---------------- GEMM: g_y = dinv * (X W) ----------------
__device__ __forceinline__ void gemm_body(const float* __restrict__ X,
                                          const float* __restrict__ W,
                                          int n0) {
    __shared__ float sW[D * D];
    __shared__ float sX[64 * RP];
    int t = threadIdx.x;
    for (int i = t; i < 1024; i += 256)
        ((float4*)sW)[i] = ((const float4*)W)[i];
    for (int i = t; i < 1024; i += 256) {
        int r = i >> 4, c4 = i & 15;
        float4 v = make_float4(0.f, 0.f, 0.f, 0.f);
        if (n0 + r < NN) v = ((const float4*)X)[(n0 + r) * 16 + c4];
        float* dst = &sX[r * RP + c4 * 4];
        dst[0] = v.x; dst[1] = v.y; dst[2] = v.z; dst[3] = v.w;
    }
    __syncthreads();

    int w = t >> 5, lane = t & 31;
    int r = (w & 1) * 32 + lane;
    int c0 = (w >> 1) * 16;
    float acc[16];
#pragma unroll
    for (int i = 0; i < 16; i++) acc[i] = 0.0f;

    const float* xrow = &sX[r * RP];
#pragma unroll
    for (int k = 0; k < D; k++) {
        float xk = xrow[k];
        const float4* wr = (const float4*)&sW[k * D + c0];
        float4 w0 = wr[0], w1 = wr[1], w2 = wr[2], w3 = wr[3];
        acc[0]  += xk * w0.x; acc[1]  += xk * w0.y;
        acc[2]  += xk * w0.z; acc[3]  += xk * w0.w;
        acc[4]  += xk * w1.x; acc[5]  += xk * w1.y;
        acc[6]  += xk * w1.z; acc[7]  += xk * w1.w;
        acc[8]  += xk * w2.x; acc[9]  += xk * w2.y;
        acc[10] += xk * w2.z; acc[11] += xk * w2.w;
        acc[12] += xk * w3.x; acc[13] += xk * w3.y;
        acc[14] += xk * w3.z; acc[15] += xk * w3.w;
    }

    int n = n0 + r;
    if (n < NN) {
        float s = g_dinv[n];
        float4* yo = (float4*)(g_y + n * D + c0);
#pragma unroll
        for (int j = 0; j < 4; j++)
            yo[j] = make_float4(s * acc[j*4], s * acc[j*4+1],
                                s * acc[j*4+2], s * acc[j*4+3]);
    }
}

__global__ void __launch_bounds__(256) k_gemm1(const float* __restrict__ X,
                                               const float* __restrict__ W) {
    gemm_body(X, W, blockIdx.x * 64);
}
__global__ void __launch_bounds__(256) k_gemm2(const float* __restrict__ W) {
    gemm_body(g_h, W, blockIdx.x * 64);
}

// ---------------- fused gather + finalize ----------------
// 16 threads per node (q = float4 chunk). acc = y[n] + sum_e y[col[e]];
// h = relu(dinv[n]*acc + b); store_h stores h; pools into pool.
__device__ __forceinline__ void gather_body(const float* __restrict__ b,
                                            const int* __restrict__ batch,
                                            float* __restrict__ pool,
                                            int store_h) {
    int idx = blockIdx.x * blockDim.x + threadIdx.x;
    int n = idx >> 4;
    int q = idx & 15;
    if (n >= NN) return;
    const float4* y4 = (const float4*)g_y;
    float4 acc = y4[n * 16 + q];                 // self loop term
    int s = g_start[n], e = g_start[n + 1];
    for (int ei = s; ei < e; ei++) {
        unsigned c = (unsigned)g_ecol[ei];
        if (c < NN) {
            float4 v = y4[c * 16 + q];
            acc.x += v.x; acc.y += v.y; acc.z += v.z; acc.w += v.w;
        }
    }
    float sc = g_dinv[n];
    float4 bb = ((const float4*)b)[q];
    float4 h;
    h.x = fmaxf(sc * acc.x + bb.x, 0.0f);
    h.y = fmaxf(sc * acc.y + bb.y, 0.0f);
    h.z = fmaxf(sc * acc.z + bb.z, 0.0f);
    h.w = fmaxf(sc * acc.w + bb.w, 0.0f);
    if (store_h) ((float4*)g_h)[n * 16 + q] = h;
    unsigned g = (unsigned)batch[n];
    if (g < NG) red_v4(((float4*)pool) + g * 16 + q, h);
}

__global__ void k_gather1(const float* __restrict__ b, const int* __restrict__ batch) {
    gather_body(b, batch, g_pool1, 1);
}
__global__ void k_gather2(const float* __restrict__ b, const int* __restrict__ batch) {
    gather_body(b, batch, g_pool2, 0);
}

// ---------------- head ----------------
__global__ void k_head(const float* __restrict__ Wl, const float* __restrict__ bl,
                       float* __restrict__ out) {
    int g = blockIdx.x;
    int lane = threadIdx.x;  // 32
    float denom = fmaxf((float)g_cnti[g], 1.0f);
    float v0 = (g_pool1[g * D + lane] + g_pool2[g * D + lane]) / denom;
    float v1 = (g_pool1[g * D + 32 + lane] + g_pool2[g * D + 32 + lane]) / denom;
    float z = (lane < NC) ? bl[lane] : 0.0f;
#pragma unroll
    for (int d = 0; d < 32; d++) {
        float a0 = __shfl_sync(0xffffffffu, v0, d);
        float a1 = __shfl_sync(0xffffffffu, v1, d);
        if (lane < NC) z += a0 * Wl[d * NC + lane] + a1 * Wl[(d + 32) * NC + lane];
    }
    if (lane < NC) z = fmaxf(z, 0.0f);
    float zm = (lane < NC) ? z : -1e30f;
#pragma unroll
    for (int off = 16; off; off >>= 1)
        zm = fmaxf(zm, __shfl_xor_sync(0xffffffffu, zm, off));
    float e = (lane < NC) ? expf(z - zm) : 0.0f;
#pragma unroll
    for (int off = 16; off; off >>= 1)
        e += __shfl_xor_sync(0xffffffffu, e, off);
    if (lane < NC) out[g * NC + lane] = z - zm - logf(e);
}

// ---------------- launch ----------------

extern "C" void kernel_launch(void* const* d_in, const int* in_sizes, int n_in,
                              void* d_out, int out_size) {
    const float* x     = (const float*)d_in[0];
    const int*   eidx  = (const int*)d_in[1];    // int32 (JAX x64 disabled)
    const int*   batch = (const int*)d_in[2];
    const float* W1    = (const float*)d_in[3];
    const float* b1    = (const float*)d_in[4];
    const float* W2    = (const float*)d_in[5];
    const float* b2    = (const float*)d_in[6];
    const float* Wl    = (const float*)d_in[7];
    const float* bl    = (const float*)d_in[8];
    float* out = (float*)d_out;

    const int* rows = eidx;        // edge_index[0] = targets
    const int* cols = eidx + NE;   // edge_index[1] = sources

    const int GB = (NN + 63) / 64;

    // degrees, dinv, per-graph counts
    k_init<<<(NN + 255) / 256, 256>>>();
    k_deg<<<(NE + 255) / 256, 256>>>(rows);
    k_prep<<<(NN + 255) / 256, 256>>>(batch);

    // CSR build (reused by both convs)
    k_scanA<<<NB, 256>>>();
    k_scanB<<<1, 512>>>();
    k_scanC<<<NB, 256>>>();
    k_fill<<<(NE + 255) / 256, 256>>>(rows, cols);

    // conv1
    k_gemm1<<<GB, 256>>>(x, W1);
    k_gather1<<<(NN * 16 + 255) / 256, 256>>>(b1, batch);

    // conv2
    k_gemm2<<<GB, 256>>>(W2);
    k_gather2<<<(NN * 16 + 255) / 256, 256>>>(b2, batch);

    // head
    k_head<<<NG, 32>>>(Wl, bl, out);
}

// round 8
// speedup vs baseline: 3.3514x; 1.1203x over previous
#include <cuda_runtime.h>

#define NN 100000
#define NE 1200000
#define NG 512
#define D  64
#define NC 10
#define RP2 68           // padded smem row: 16B-aligned, conflict-free rg spacing
#define NB 391           // scan blocks = ceil(NN/256)

// ---------------- scratch (device globals; no allocation) ----------------
__device__ int   g_degi[NN];
__device__ float g_dinv[NN];
__device__ float g_y[NN * D];     // scaled linear output  dinv[n] * (X W)[n]
__device__ float g_h[NN * D];     // layer-1 activations
__device__ float g_pool1[NG * D];
__device__ float g_pool2[NG * D];
__device__ int   g_cnti[NG];
// CSR
__device__ int   g_scan[NN];
__device__ int   g_bsum[NB];
__device__ int   g_boff[NB];
__device__ int   g_start[NN + 1];
__device__ int   g_pos[NN];
__device__ int   g_ecol[NE];

__device__ __forceinline__ void red_v4(float4* dst, float4 v) {
    asm volatile("red.global.add.v4.f32 [%0], {%1,%2,%3,%4};"
                 :: "l"(dst), "f"(v.x), "f"(v.y), "f"(v.z), "f"(v.w) : "memory");
}

// ---------------- setup kernels ----------------

__global__ void k_init() {
    int i = blockIdx.x * blockDim.x + threadIdx.x;
    if (i < NN) g_degi[i] = 0;
    if (i < NG * D) { g_pool1[i] = 0.0f; g_pool2[i] = 0.0f; }
    if (i < NG) g_cnti[i] = 0;
}

__global__ void k_deg(const int* __restrict__ rows) {
    int e = blockIdx.x * blockDim.x + threadIdx.x;
    if (e >= NE) return;
    unsigned r = (unsigned)rows[e];
    if (r < NN) atomicAdd(&g_degi[r], 1);
}

__global__ void k_prep(const int* __restrict__ batch) {
    int i = blockIdx.x * blockDim.x + threadIdx.x;
    if (i >= NN) return;
    g_dinv[i] = rsqrtf((float)g_degi[i] + 1.0f);   // +1 = self loop
    unsigned g = (unsigned)batch[i];
    if (g < NG) atomicAdd(&g_cnti[g], 1);
}

// per-block inclusive scan of degrees
__global__ void k_scanA() {
    __shared__ int s[256];
    int t = threadIdx.x;
    int i = blockIdx.x * 256 + t;
    int d = (i < NN) ? g_degi[i] : 0;
    s[t] = d;
    __syncthreads();
#pragma unroll
    for (int off = 1; off < 256; off <<= 1) {
        int v = (t >= off) ? s[t - off] : 0;
        __syncthreads();
        s[t] += v;
        __syncthreads();
    }
    if (i < NN) g_scan[i] = s[t];
    if (t == 255) g_bsum[blockIdx.x] = s[255];
}

// single-block exclusive scan of block sums
__global__ void k_scanB() {
    __shared__ int s[512];
    int t = threadIdx.x;  // 512
    s[t] = (t < NB) ? g_bsum[t] : 0;
    __syncthreads();
#pragma unroll
    for (int off = 1; off < 512; off <<= 1) {
        int v = (t >= off) ? s[t - off] : 0;
        __syncthreads();
        s[t] += v;
        __syncthreads();
    }
    if (t < NB) g_boff[t] = (t == 0) ? 0 : s[t - 1];
    if (t == 511) g_start[NN] = s[511];
}

__global__ void k_scanC() {
    int i = blockIdx.x * blockDim.x + threadIdx.x;
    if (i >= NN) return;
    int st = g_scan[i] - g_degi[i] + g_boff[i >> 8];
    g_start[i] = st;
    g_pos[i] = st;
}

__global__ void k_fill(const int* __restrict__ rows, const int* __restrict__ cols) {
    int e = blockIdx.x * blockDim.x + threadIdx.x;
    if (e >= NE) return;
    unsigned r = (unsigned)rows[e];
    if (r >= NN) return;
    int p = atomicAdd(&g_pos[r], 1);
    g_ecol[p] = cols[e];
}

// ---------------- GEMM: g_y = dinv * (X W) ----------------
// Block: 256 thr, tile 128 rows x 64 cols. Warp (w&3)=row strip of 32,
// (w>>2)=col strip of 32. Thread: 8 rows (stride-4 interleaved) x 4 cols.
// Per 4-k step: 8 x-LDS.128 + 4 W-LDS.128 -> 128 FFMA.
__device__ __forceinline__ void gemm_body(const float* __restrict__ X,
                                          const float* __restrict__ W,
                                          int n0) {
    __shared__ float sW[D * D];
    __shared__ float sX[128 * RP2];
    int t = threadIdx.x;
    for (int i = t; i < 1024; i += 256)
        ((float4*)sW)[i] = ((const float4*)W)[i];
    for (int i = t; i < 2048; i += 256) {
        int r = i >> 4, c4 = i & 15;
        float4 v = make_float4(0.f, 0.f, 0.f, 0.f);
        if (n0 + r < NN) v = ((const float4*)X)[(n0 + r) * 16 + c4];
        *(float4*)&sX[r * RP2 + c4 * 4] = v;
    }
    __syncthreads();

    int w = t >> 5, lane = t & 31;
    int wr = (w & 3) * 32;
    int wc = (w >> 2) * 32;
    int rg = lane >> 3;          // 0..3
    int cg = lane & 7;           // 0..7
    int c  = wc + cg * 4;

    float4 acc[8];
#pragma unroll
    for (int j = 0; j < 8; j++) acc[j] = make_float4(0.f, 0.f, 0.f, 0.f);

#pragma unroll 4
    for (int k4 = 0; k4 < 16; k4++) {
        float4 wv0 = *(const float4*)&sW[(k4 * 4 + 0) * D + c];
        float4 wv1 = *(const float4*)&sW[(k4 * 4 + 1) * D + c];
        float4 wv2 = *(const float4*)&sW[(k4 * 4 + 2) * D + c];
        float4 wv3 = *(const float4*)&sW[(k4 * 4 + 3) * D + c];
#pragma unroll
        for (int j = 0; j < 8; j++) {
            float4 xv = *(const float4*)&sX[(wr + rg + 4 * j) * RP2 + k4 * 4];
            acc[j].x += xv.x * wv0.x + xv.y * wv1.x + xv.z * wv2.x + xv.w * wv3.x;
            acc[j].y += xv.x * wv0.y + xv.y * wv1.y + xv.z * wv2.y + xv.w * wv3.y;
            acc[j].z += xv.x * wv0.z + xv.y * wv1.z + xv.z * wv2.z + xv.w * wv3.z;
            acc[j].w += xv.x * wv0.w + xv.y * wv1.w + xv.z * wv2.w + xv.w * wv3.w;
        }
    }

#pragma unroll
    for (int j = 0; j < 8; j++) {
        int n = n0 + wr + rg + 4 * j;
        if (n < NN) {
            float s = g_dinv[n];
            ((float4*)g_y)[n * 16 + (c >> 2)] =
                make_float4(s * acc[j].x, s * acc[j].y, s * acc[j].z, s * acc[j].w);
        }
    }
}

__global__ void __launch_bounds__(256) k_gemm1(const float* __restrict__ X,
                                               const float* __restrict__ W) {
    gemm_body(X, W, blockIdx.x * 128);
}
__global__ void __launch_bounds__(256) k_gemm2(const float* __restrict__ W) {
    gemm_body(g_h, W, blockIdx.x * 128);
}

// ---------------- fused gather + finalize ----------------
__device__ __forceinline__ void gather_body(const float* __restrict__ b,
                                            const int* __restrict__ batch,
                                            float* __restrict__ pool,
                                            int store_h) {
    int idx = blockIdx.x * blockDim.x + threadIdx.x;
    int n = idx >> 4;
    int q = idx & 15;
    if (n >= NN) return;
    const float4* y4 = (const float4*)g_y;
    float4 acc = y4[n * 16 + q];                 // self loop term
    int s = g_start[n], e = g_start[n + 1];
    for (int ei = s; ei < e; ei++) {
        unsigned c = (unsigned)g_ecol[ei];
        if (c < NN) {
            float4 v = y4[c * 16 + q];
            acc.x += v.x; acc.y += v.y; acc.z += v.z; acc.w += v.w;
        }
    }
    float sc = g_dinv[n];
    float4 bb = ((const float4*)b)[q];
    float4 h;
    h.x = fmaxf(sc * acc.x + bb.x, 0.0f);
    h.y = fmaxf(sc * acc.y + bb.y, 0.0f);
    h.z = fmaxf(sc * acc.z + bb.z, 0.0f);
    h.w = fmaxf(sc * acc.w + bb.w, 0.0f);
    if (store_h) ((float4*)g_h)[n * 16 + q] = h;
    unsigned g = (unsigned)batch[n];
    if (g < NG) red_v4(((float4*)pool) + g * 16 + q, h);
}

__global__ void k_gather1(const float* __restrict__ b, const int* __restrict__ batch) {
    gather_body(b, batch, g_pool1, 1);
}
__global__ void k_gather2(const float* __restrict__ b, const int* __restrict__ batch) {
    gather_body(b, batch, g_pool2, 0);
}

// ---------------- head ----------------
__global__ void k_head(const float* __restrict__ Wl, const float* __restrict__ bl,
                       float* __restrict__ out) {
    int g = blockIdx.x;
    int lane = threadIdx.x;  // 32
    float denom = fmaxf((float)g_cnti[g], 1.0f);
    float v0 = (g_pool1[g * D + lane] + g_pool2[g * D + lane]) / denom;
    float v1 = (g_pool1[g * D + 32 + lane] + g_pool2[g * D + 32 + lane]) / denom;
    float z = (lane < NC) ? bl[lane] : 0.0f;
#pragma unroll
    for (int d = 0; d < 32; d++) {
        float a0 = __shfl_sync(0xffffffffu, v0, d);
        float a1 = __shfl_sync(0xffffffffu, v1, d);
        if (lane < NC) z += a0 * Wl[d * NC + lane] + a1 * Wl[(d + 32) * NC + lane];
    }
    if (lane < NC) z = fmaxf(z, 0.0f);
    float zm = (lane < NC) ? z : -1e30f;
#pragma unroll
    for (int off = 16; off; off >>= 1)
        zm = fmaxf(zm, __shfl_xor_sync(0xffffffffu, zm, off));
    float e = (lane < NC) ? expf(z - zm) : 0.0f;
#pragma unroll
    for (int off = 16; off; off >>= 1)
        e += __shfl_xor_sync(0xffffffffu, e, off);
    if (lane < NC) out[g * NC + lane] = z - zm - logf(e);
}

// ---------------- launch ----------------

extern "C" void kernel_launch(void* const* d_in, const int* in_sizes, int n_in,
                              void* d_out, int out_size) {
    const float* x     = (const float*)d_in[0];
    const int*   eidx  = (const int*)d_in[1];    // int32 (JAX x64 disabled)
    const int*   batch = (const int*)d_in[2];
    const float* W1    = (const float*)d_in[3];
    const float* b1    = (const float*)d_in[4];
    const float* W2    = (const float*)d_in[5];
    const float* b2    = (const float*)d_in[6];
    const float* Wl    = (const float*)d_in[7];
    const float* bl    = (const float*)d_in[8];
    float* out = (float*)d_out;

    const int* rows = eidx;        // edge_index[0] = targets
    const int* cols = eidx + NE;   // edge_index[1] = sources

    const int GB = (NN + 127) / 128;   // 782 gemm blocks

    // degrees, dinv, per-graph counts
    k_init<<<(NN + 255) / 256, 256>>>();
    k_deg<<<(NE + 255) / 256, 256>>>(rows);
    k_prep<<<(NN + 255) / 256, 256>>>(batch);

    // CSR build (reused by both convs)
    k_scanA<<<NB, 256>>>();
    k_scanB<<<1, 512>>>();
    k_scanC<<<NB, 256>>>();
    k_fill<<<(NE + 255) / 256, 256>>>(rows, cols);

    // conv1
    k_gemm1<<<GB, 256>>>(x, W1);
    k_gather1<<<(NN * 16 + 255) / 256, 256>>>(b1, batch);

    // conv2
    k_gemm2<<<GB, 256>>>(W2);
    k_gather2<<<(NN * 16 + 255) / 256, 256>>>(b2, batch);

    // head
    k_head<<<NG, 32>>>(Wl, bl, out);
}